// round 2
// baseline (speedup 1.0000x reference)
#include <cuda_runtime.h>

#define RS2 0.70710678118654752440f  // 1/sqrt(2)

__device__ __forceinline__ float sx(float v, int m) {
    return __shfl_xor_sync(0xFFFFFFFFu, v, m, 32);
}

// Fused step G_q = CNOT * CRX * (H x I) on bits (LO, HI), both register bits.
// Per 4-group (x1=bit HI, x0=bit LO):
//   H on LO, then where x0==1: new a[x1][1] = s*self + c*partner  (s = -i*sin)
template<int LO, int HI>
__device__ __forceinline__ void step_local(float (&sr)[16], float (&si)[16],
                                           float c, float sn) {
    constexpr int L0 = 1 << LO, L1 = 1 << HI;
#pragma unroll
    for (int m = 0; m < 16; ++m) {
        if (m & (L0 | L1)) continue;
        const int i00 = m, i01 = m | L0, i10 = m | L1, i11 = m | L0 | L1;
        // H on LO (two pairs)
        float ar = sr[i00], ai = si[i00], br = sr[i01], bi = si[i01];
        sr[i00] = (ar + br) * RS2; si[i00] = (ai + bi) * RS2;
        sr[i01] = (ar - br) * RS2; si[i01] = (ai - bi) * RS2;
        float cr = sr[i10], ci = si[i10], dr = sr[i11], di = si[i11];
        sr[i10] = (cr + dr) * RS2; si[i10] = (ci + di) * RS2;
        sr[i11] = (cr - dr) * RS2; si[i11] = (ci - di) * RS2;
        // CRX + CNOT on (i01, i11): u, v -> (s*u + c*v, c*u + s*v)
        float ur = sr[i01], ui = si[i01], vr = sr[i11], vi = si[i11];
        sr[i01] =  sn * ui + c * vr;  si[i01] = -sn * ur + c * vi;
        sr[i11] =  c * ur + sn * vi;  si[i11] =  c * ui - sn * vr;
    }
}

// Step with LO = register bit, HI = lane bit (mask M). CNOT included.
template<int LO>
__device__ __forceinline__ void step_regA(float (&sr)[16], float (&si)[16],
                                          float c, float sn, int M) {
    constexpr int L0 = 1 << LO;
#pragma unroll
    for (int m = 0; m < 16; ++m) {  // H on LO (local)
        if (m & L0) continue;
        const int i0 = m, i1 = m | L0;
        float ar = sr[i0], ai = si[i0], br = sr[i1], bi = si[i1];
        sr[i0] = (ar + br) * RS2; si[i0] = (ai + bi) * RS2;
        sr[i1] = (ar - br) * RS2; si[i1] = (ai - bi) * RS2;
    }
#pragma unroll
    for (int m = 0; m < 16; ++m) {  // CRX+CNOT across lane bit M where LO==1
        if (!(m & L0)) continue;
        float mr = sr[m], mi = si[m];
        float pr = sx(mr, M), pi = sx(mi, M);
        sr[m] =  sn * mi + c * pr;
        si[m] = -sn * mr + c * pi;
    }
}

// Step with both bits in lane bits (masks M0=low/control, M1=high/target). CNOT included.
__device__ __forceinline__ void step_laneB(float (&sr)[16], float (&si)[16],
                                           float c, float sn, int M0, int M1, int lane) {
    const bool hb = (lane & M0) != 0;
#pragma unroll
    for (int m = 0; m < 16; ++m) {  // H across lane bit M0
        float mr = sr[m], mi = si[m];
        float pr = sx(mr, M0), pi = sx(mi, M0);
        sr[m] = hb ? (pr - mr) * RS2 : (mr + pr) * RS2;
        si[m] = hb ? (pi - mi) * RS2 : (mi + pi) * RS2;
    }
#pragma unroll
    for (int m = 0; m < 16; ++m) {  // CRX+CNOT across lane bit M1 where M0 bit == 1
        float mr = sr[m], mi = si[m];
        float pr = sx(mr, M1), pi = sx(mi, M1);
        if (hb) {
            sr[m] =  sn * mi + c * pr;
            si[m] = -sn * mr + c * pi;
        }
    }
}

// Final step q=11: H on bit 11 (reg bit 3), CRX control bit11 target bit0 (lane bit 0), NO CNOT.
// RX is symmetric: new = c*self + s*partner.
__device__ __forceinline__ void step_final(float (&sr)[16], float (&si)[16],
                                           float c, float sn) {
#pragma unroll
    for (int m = 0; m < 8; ++m) {  // H on reg bit 3
        const int i0 = m, i1 = m | 8;
        float ar = sr[i0], ai = si[i0], br = sr[i1], bi = si[i1];
        sr[i0] = (ar + br) * RS2; si[i0] = (ai + bi) * RS2;
        sr[i1] = (ar - br) * RS2; si[i1] = (ai - bi) * RS2;
    }
#pragma unroll
    for (int m = 8; m < 16; ++m) {  // CRX across lane bit 0 where bit11==1
        float mr = sr[m], mi = si[m];
        float pr = sx(mr, 1), pi = sx(mi, 1);
        sr[m] = c * mr + sn * pi;
        si[m] = c * mi - sn * pr;
    }
}

__global__ __launch_bounds__(256)
void quantum_kernel(const float* __restrict__ x,
                    const float* __restrict__ params,
                    float* __restrict__ out) {
    __shared__ float2 buf[4096];     // transpose buffer (32 KB)
    __shared__ float2 cs[16];        // (cos, sin) of params[q]/2
    __shared__ float redsum[8], redcnt[8];
    __shared__ float s_ninv, s_invn2;

    const int tid  = threadIdx.x;
    const int lane = tid & 31;
    const int warp = tid >> 5;
    const int row  = blockIdx.x;
    const float* xr = x + (size_t)row * 4096;

    float sr[16], si[16];

    // Load 16 consecutive floats: index bits 0-3 = register slot, 4-11 = tid
#pragma unroll
    for (int r = 0; r < 16; r += 4) {
        float4 v = *reinterpret_cast<const float4*>(xr + tid * 16 + r);
        sr[r] = v.x; sr[r + 1] = v.y; sr[r + 2] = v.z; sr[r + 3] = v.w;
    }

    // Block reduction: sum of squares + nonzero count
    float ss = 0.f, cnt = 0.f;
#pragma unroll
    for (int r = 0; r < 16; ++r) {
        ss += sr[r] * sr[r];
        cnt += (sr[r] != 0.0f) ? 1.0f : 0.0f;
    }
#pragma unroll
    for (int m = 16; m >= 1; m >>= 1) { ss += sx(ss, m); cnt += sx(cnt, m); }
    if (lane == 0) { redsum[warp] = ss; redcnt[warp] = cnt; }
    if (tid < 12) {
        float th = params[tid] * 0.5f;
        cs[tid] = make_float2(cosf(th), sinf(th));
    }
    __syncthreads();
    if (tid == 0) {
        float S = 0.f, C = 0.f;
#pragma unroll
        for (int w = 0; w < 8; ++w) { S += redsum[w]; C += redcnt[w]; }
        s_ninv  = 1.0f / (sqrtf(S) + 1e-8f);
        s_invn2 = (C > 0.f) ? (1.0f / C) : 0.0f;
    }
    __syncthreads();
    const float ninv = s_ninv, invn2 = s_invn2;

    // _to_quantum (unnormalized; 1/||q||^2 folded into output probs)
#pragma unroll
    for (int r = 0; r < 16; ++r) {
        float xv  = sr[r];
        float v   = xv * ninv;
        float mag = fminf(fabsf(v), 1.0f);
        float sgn = (xv > 0.f) ? 1.f : ((xv < 0.f) ? -1.f : 0.f);
        sr[r] = sgn * mag;
        si[r] = sgn * sqrtf(fmaxf(1.0f - mag * mag, 0.0f));
    }

    // Gates: bits 0-3 in registers, 4-8 in lane, 9-11 in warp id
    float2 g;
    g = cs[0]; step_local<0, 1>(sr, si, g.x, g.y);
    g = cs[1]; step_local<1, 2>(sr, si, g.x, g.y);
    g = cs[2]; step_local<2, 3>(sr, si, g.x, g.y);
    g = cs[3]; step_regA<3>(sr, si, g.x, g.y, 1);
    g = cs[4]; step_laneB(sr, si, g.x, g.y, 1, 2, lane);
    g = cs[5]; step_laneB(sr, si, g.x, g.y, 2, 4, lane);
    g = cs[6]; step_laneB(sr, si, g.x, g.y, 4, 8, lane);
    g = cs[7]; step_laneB(sr, si, g.x, g.y, 8, 16, lane);

    // Transpose: bits 8-11 -> register slot, bits 0-7 -> tid. XOR-swizzle banks.
#pragma unroll
    for (int r = 0; r < 16; ++r) {
        int i = tid * 16 + r;
        int j = i ^ ((i >> 4) & 15);
        buf[j] = make_float2(sr[r], si[r]);
    }
    __syncthreads();
#pragma unroll
    for (int r = 0; r < 16; ++r) {
        int i = (r << 8) | tid;
        int j = i ^ ((i >> 4) & 15);
        float2 f = buf[j];
        sr[r] = f.x; si[r] = f.y;
    }

    g = cs[8];  step_local<0, 1>(sr, si, g.x, g.y);   // bits (8,9)
    g = cs[9];  step_local<1, 2>(sr, si, g.x, g.y);   // bits (9,10)
    g = cs[10]; step_local<2, 3>(sr, si, g.x, g.y);   // bits (10,11)
    g = cs[11]; step_final(sr, si, g.x, g.y);         // bits (11,0), no CNOT

    // Output probabilities: index = (r<<8)|tid  (coalesced per warp per r)
    float* orow = out + (size_t)row * 4096;
#pragma unroll
    for (int r = 0; r < 16; ++r) {
        orow[(r << 8) | tid] = (sr[r] * sr[r] + si[r] * si[r]) * invn2;
    }
}

extern "C" void kernel_launch(void* const* d_in, const int* in_sizes, int n_in,
                              void* d_out, int out_size) {
    const float* state  = (const float*)d_in[0];
    const float* params = (const float*)d_in[1];
    float* out = (float*)d_out;
    int rows = in_sizes[0] / 4096;   // 8*512 = 4096
    quantum_kernel<<<rows, 256>>>(state, params, out);
}